// round 14
// baseline (speedup 1.0000x reference)
#include <cuda_runtime.h>
#include <cuda_bf16.h>

// ---------------------------------------------------------------------------
// Problem constants (fixed by setup_inputs)
// ---------------------------------------------------------------------------
#define BATCH   4
#define N_DAY   2048
#define N_CELLS 8192
#define D_MICRO 11
#define D_MODEL 256
#define TOPK    32

#define NQ   (BATCH * N_DAY)    // 8192 query rows (flattened)
#define NKV  (BATCH * N_CELLS)  // 32768 key/value rows (flattened)

#define NEG_BIG (-3.402823466e38f)

// ---------------------------------------------------------------------------
// Device scratch (static allocation is the sanctioned workaround)
// ---------------------------------------------------------------------------
__device__ float g_xmicro[NQ * D_MODEL];                     //  8 MB
__device__ float g_q     [NQ * D_MODEL];                     //  8 MB
__device__ float g_k     [NKV * D_MODEL];                    // 32 MB
__device__ float g_v     [NKV * D_MODEL];                    // 32 MB
__device__ float g_scores[(long)BATCH * N_DAY * N_CELLS];    // 268 MB
__device__ float g_ctx   [NQ * D_MODEL];                     //  8 MB
__device__ int   g_tidx  [NQ * TOPK];

// ---------------------------------------------------------------------------
// Kernel 1: x_micro = micro @ mp_w + mp_b   (K=11, trivial)
// One block per row, 256 threads = one output column each.
// ---------------------------------------------------------------------------
__global__ void micro_proj_kernel(const float* __restrict__ micro,
                                  const float* __restrict__ w,
                                  const float* __restrict__ b,
                                  float* __restrict__ out)
{
    __shared__ float xs[D_MICRO];
    const int row = blockIdx.x;
    const int t   = threadIdx.x;
    if (t < D_MICRO) xs[t] = micro[row * D_MICRO + t];
    __syncthreads();
    float acc = b[t];
#pragma unroll
    for (int i = 0; i < D_MICRO; i++)
        acc = fmaf(xs[i], w[i * D_MODEL + t], acc);
    out[(long)row * D_MODEL + t] = acc;
}

// ---------------------------------------------------------------------------
// Generic fp32 GEMM: C[M,N] = A[M,K] * op(B) (+bias) (+resid)
//   TRANSB=false: B is [K,N] row-major (projections)
//   TRANSB=true : B is [N,K] row-major (scores: Q @ K^T)
// Tile 128x128x16, 256 threads, 8x8 per-thread micro-tile.
// All problem dims are multiples of the tile sizes -> no bounds checks.
// Batched via blockIdx.z with explicit strides.
// ---------------------------------------------------------------------------
#define BM 128
#define BN 128
#define BK 16

template <bool TRANSB, bool BIAS, bool RESID>
__global__ __launch_bounds__(256)
void gemm_kernel(const float* __restrict__ A,
                 const float* __restrict__ Bm,
                 const float* __restrict__ bias,
                 const float* __restrict__ resid,
                 float* __restrict__ C,
                 int M, int N, int K,
                 long aBS, long bBS, long cBS)
{
    __shared__ float As[BK][BM + 4];   // stride 132 floats = 528B, 16B-aligned rows
    __shared__ float Bs[BK][BN + 4];

    const int tid = threadIdx.x;
    const int tx  = tid & 15;          // 0..15
    const int ty  = tid >> 4;          // 0..15
    const int m0  = blockIdx.y * BM;
    const int n0  = blockIdx.x * BN;

    A  += (long)blockIdx.z * aBS;
    Bm += (long)blockIdx.z * bBS;
    C  += (long)blockIdx.z * cBS;

    float acc[8][8];
#pragma unroll
    for (int i = 0; i < 8; i++)
#pragma unroll
        for (int j = 0; j < 8; j++) acc[i][j] = 0.0f;

    for (int k0 = 0; k0 < K; k0 += BK) {
        // ---- load A tile (128 x 16), transposed into As[kk][m] ----
        {
            const int kk   = (tid & 3) * 4;
            const int mrow = tid >> 2;          // 0..63
#pragma unroll
            for (int p = 0; p < 2; p++) {
                const int m = mrow + p * 64;
                float4 v = *reinterpret_cast<const float4*>(
                    &A[(long)(m0 + m) * K + k0 + kk]);
                As[kk + 0][m] = v.x;
                As[kk + 1][m] = v.y;
                As[kk + 2][m] = v.z;
                As[kk + 3][m] = v.w;
            }
        }
        // ---- load B tile into Bs[kk][n] ----
        if (TRANSB) {
            const int kk   = (tid & 3) * 4;
            const int nrow = tid >> 2;          // 0..63
#pragma unroll
            for (int p = 0; p < 2; p++) {
                const int n = nrow + p * 64;
                float4 v = *reinterpret_cast<const float4*>(
                    &Bm[(long)(n0 + n) * K + k0 + kk]);
                Bs[kk + 0][n] = v.x;
                Bs[kk + 1][n] = v.y;
                Bs[kk + 2][n] = v.z;
                Bs[kk + 3][n] = v.w;
            }
        } else {
            const int ncol = (tid & 31) * 4;    // 0..124
            const int kk   = tid >> 5;          // 0..7
#pragma unroll
            for (int p = 0; p < 2; p++) {
                float4 v = *reinterpret_cast<const float4*>(
                    &Bm[(long)(k0 + kk + p * 8) * N + n0 + ncol]);
                *reinterpret_cast<float4*>(&Bs[kk + p * 8][ncol]) = v;
            }
        }
        __syncthreads();

        // ---- compute ----
#pragma unroll
        for (int kk = 0; kk < BK; kk++) {
            float4 a0 = *reinterpret_cast<const float4*>(&As[kk][ty * 4]);
            float4 a1 = *reinterpret_cast<const float4*>(&As[kk][64 + ty * 4]);
            float4 b0 = *reinterpret_cast<const float4*>(&Bs[kk][tx * 4]);
            float4 b1 = *reinterpret_cast<const float4*>(&Bs[kk][64 + tx * 4]);
            float a[8] = {a0.x, a0.y, a0.z, a0.w, a1.x, a1.y, a1.z, a1.w};
            float b[8] = {b0.x, b0.y, b0.z, b0.w, b1.x, b1.y, b1.z, b1.w};
#pragma unroll
            for (int i = 0; i < 8; i++)
#pragma unroll
                for (int j = 0; j < 8; j++)
                    acc[i][j] = fmaf(a[i], b[j], acc[i][j]);
        }
        __syncthreads();
    }

    // ---- epilogue (float4 stores) ----
#pragma unroll
    for (int ih = 0; ih < 2; ih++) {
#pragma unroll
        for (int i = 0; i < 4; i++) {
            const long mr = m0 + ih * 64 + ty * 4 + i;
#pragma unroll
            for (int jh = 0; jh < 2; jh++) {
                const int nc = n0 + jh * 64 + tx * 4;
                float4 r;
                r.x = acc[ih * 4 + i][jh * 4 + 0];
                r.y = acc[ih * 4 + i][jh * 4 + 1];
                r.z = acc[ih * 4 + i][jh * 4 + 2];
                r.w = acc[ih * 4 + i][jh * 4 + 3];
                if (BIAS) {
                    float4 bb = *reinterpret_cast<const float4*>(&bias[nc]);
                    r.x += bb.x; r.y += bb.y; r.z += bb.z; r.w += bb.w;
                }
                if (RESID) {
                    float4 rr = *reinterpret_cast<const float4*>(&resid[mr * N + nc]);
                    r.x += rr.x; r.y += rr.y; r.z += rr.z; r.w += rr.w;
                }
                *reinterpret_cast<float4*>(&C[mr * N + nc]) = r;
            }
        }
    }
}

// ---------------------------------------------------------------------------
// Kernel: per-query top-32 (descending, stable/smaller-index tie-break,
// matching jax.lax.top_k) + softmax. Writes attn weights + indices directly.
// One block (256 threads) per query row; each thread caches 32 scores in regs.
// ---------------------------------------------------------------------------
__global__ __launch_bounds__(256)
void topk_kernel(const float* __restrict__ scores,
                 float* __restrict__ attnw_out,     // [NQ, TOPK] (d_out section 1)
                 float* __restrict__ idxf_out,      // [NQ, TOPK] (d_out section 2)
                 int*   __restrict__ idx_out)       // [NQ, TOPK] scratch for gather
{
    const int   q     = blockIdx.x;   // 0..NQ-1
    const int   t     = threadIdx.x;  // 0..255
    const float scale = 0.0625f;      // 256^-0.5 (exact)

    const float* s = scores + (long)q * N_CELLS;

    float v[32];
#pragma unroll
    for (int i = 0; i < 32; i++)
        v[i] = s[i * 256 + t] * scale;   // coalesced; scale before topk (monotonic)

    __shared__ float warp_v[8];
    __shared__ int   warp_i[8];
    __shared__ float sel_v[TOPK];
    __shared__ int   sel_i[TOPK];
    __shared__ int   bcast_i;

    const int lane = t & 31;
    const int wrp  = t >> 5;

    for (int k = 0; k < TOPK; k++) {
        // local argmax over 32 cached values (index grows with slot -> strict >
        // keeps smallest index on ties)
        float bv    = v[0];
        int   bslot = 0;
#pragma unroll
        for (int i = 1; i < 32; i++)
            if (v[i] > bv) { bv = v[i]; bslot = i; }
        int bidx = bslot * 256 + t;

        // warp-shuffle argmax reduction with smaller-index tie-break
#pragma unroll
        for (int o = 16; o > 0; o >>= 1) {
            float ov = __shfl_down_sync(0xffffffffu, bv, o);
            int   oi = __shfl_down_sync(0xffffffffu, bidx, o);
            if (ov > bv || (ov == bv && oi < bidx)) { bv = ov; bidx = oi; }
        }
        if (lane == 0) { warp_v[wrp] = bv; warp_i[wrp] = bidx; }
        __syncthreads();

        if (t == 0) {
            float gv = warp_v[0];
            int   gi = warp_i[0];
#pragma unroll
            for (int w = 1; w < 8; w++) {
                if (warp_v[w] > gv || (warp_v[w] == gv && warp_i[w] < gi)) {
                    gv = warp_v[w];
                    gi = warp_i[w];
                }
            }
            sel_v[k] = gv;
            sel_i[k] = gi;
            bcast_i  = gi;
        }
        __syncthreads();

        const int gi = bcast_i;
        if ((gi & 255) == t) v[gi >> 8] = NEG_BIG;   // owner removes winner
    }

    // softmax over the 32 selected (sel_v[0] is the max by construction)
    if (t < TOPK) {
        float e   = expf(sel_v[t] - sel_v[0]);
        float sum = e;
#pragma unroll
        for (int o = 16; o > 0; o >>= 1)
            sum += __shfl_xor_sync(0xffffffffu, sum, o);
        const long o = (long)q * TOPK + t;
        attnw_out[o] = e / sum;
        idxf_out[o]  = (float)sel_i[t];
        idx_out[o]   = sel_i[t];
    }
}

// ---------------------------------------------------------------------------
// Kernel: context[q,:] = sum_k attn[q,k] * V_full[b, idx[q,k], :]
// (uses V_full = macro @ wv; equals reference gather-then-project by linearity)
// ---------------------------------------------------------------------------
__global__ __launch_bounds__(256)
void context_kernel(const float* __restrict__ V,
                    const float* __restrict__ attnw,
                    const int*   __restrict__ idx,
                    float* __restrict__ ctx)
{
    const int q = blockIdx.x;
    const int t = threadIdx.x;       // = output column d
    const int b = q >> 11;           // q / N_DAY

    __shared__ float w[TOPK];
    __shared__ int   id[TOPK];
    if (t < TOPK) {
        w[t]  = attnw[(long)q * TOPK + t];
        id[t] = idx[(long)q * TOPK + t];
    }
    __syncthreads();

    float acc = 0.0f;
#pragma unroll
    for (int k = 0; k < TOPK; k++)
        acc = fmaf(w[k], V[((long)b * N_CELLS + id[k]) * D_MODEL + t], acc);
    ctx[(long)q * D_MODEL + t] = acc;
}

// ---------------------------------------------------------------------------
// Launcher (graph-capturable: kernel launches + symbol-address lookups only)
// ---------------------------------------------------------------------------
extern "C" void kernel_launch(void* const* d_in, const int* in_sizes, int n_in,
                              void* d_out, int out_size)
{
    const float* micro = (const float*)d_in[0];
    const float* macro = (const float*)d_in[1];
    const float* mp_w  = (const float*)d_in[2];
    const float* mp_b  = (const float*)d_in[3];
    const float* wq    = (const float*)d_in[4];
    const float* wk    = (const float*)d_in[5];
    const float* wv    = (const float*)d_in[6];
    const float* op_w  = (const float*)d_in[7];
    const float* op_b  = (const float*)d_in[8];

    float* out      = (float*)d_out;
    float* out_x    = out;                                  // [B,Nd,D]
    float* out_attn = out + (size_t)NQ * D_MODEL;           // [B,Nd,K]
    float* out_idxf = out_attn + (size_t)NQ * TOPK;         // [B,Nd,K] as float

    // resolve scratch symbols (host API, no stream work -> capture-safe)
    float *xm, *qb, *kb, *vb, *sc, *cx; int* ti;
    cudaGetSymbolAddress((void**)&xm, g_xmicro);
    cudaGetSymbolAddress((void**)&qb, g_q);
    cudaGetSymbolAddress((void**)&kb, g_k);
    cudaGetSymbolAddress((void**)&vb, g_v);
    cudaGetSymbolAddress((void**)&sc, g_scores);
    cudaGetSymbolAddress((void**)&cx, g_ctx);
    cudaGetSymbolAddress((void**)&ti, g_tidx);

    const dim3 blk(256);

    // 1) x_micro
    micro_proj_kernel<<<NQ, blk>>>(micro, mp_w, mp_b, xm);

    // 2) Q = x_micro @ wq                [8192,256] = [8192,256]x[256,256]
    gemm_kernel<false, false, false><<<dim3(D_MODEL / BN, NQ / BM, 1), blk>>>(
        xm, wq, nullptr, nullptr, qb, NQ, D_MODEL, D_MODEL, 0, 0, 0);

    // 3) K_full = macro @ wk             [32768,256]
    gemm_kernel<false, false, false><<<dim3(D_MODEL / BN, NKV / BM, 1), blk>>>(
        macro, wk, nullptr, nullptr, kb, NKV, D_MODEL, D_MODEL, 0, 0, 0);

    // 4) V_full = macro @ wv             [32768,256]
    gemm_kernel<false, false, false><<<dim3(D_MODEL / BN, NKV / BM, 1), blk>>>(
        macro, wv, nullptr, nullptr, vb, NKV, D_MODEL, D_MODEL, 0, 0, 0);

    // 5) scores[b] = Q[b] @ K[b]^T       per-batch [2048,8192], dominant GEMM
    gemm_kernel<true, false, false><<<dim3(N_CELLS / BN, N_DAY / BM, BATCH), blk>>>(
        qb, kb, nullptr, nullptr, sc, N_DAY, N_CELLS, D_MODEL,
        (long)N_DAY * D_MODEL, (long)N_CELLS * D_MODEL, (long)N_DAY * N_CELLS);

    // 6) top-32 + softmax -> attn weights + indices
    topk_kernel<<<NQ, blk>>>(sc, out_attn, out_idxf, ti);

    // 7) context = attn-weighted gather of V_full
    context_kernel<<<NQ, blk>>>(vb, out_attn, ti, cx);

    // 8) x_conditioned = x_micro + ctx @ op_w + op_b  -> d_out section 0
    gemm_kernel<false, true, true><<<dim3(D_MODEL / BN, NQ / BM, 1), blk>>>(
        cx, op_w, op_b, xm, out_x, NQ, D_MODEL, D_MODEL, 0, 0, 0);

    (void)in_sizes; (void)n_in; (void)out_size;
}